// round 1
// baseline (speedup 1.0000x reference)
#include <cuda_runtime.h>
#include <cstdint>

// Problem constants (fixed by the dataset)
#define B_ROWS   65536
#define K1       1024
#define K2       512
#define K3       768
#define KTOT     (K1 + K2 + K3)        // 2304
#define NPAIRS   (KTOT / 2)            // 1152 k-pairs
#define RANK     10
#define OUTDIM   512

#define THREADS  128
#define ROWS_PER_BLOCK (2 * THREADS)   // 256 rows, 2 per thread
#define GRID     (B_ROWS / ROWS_PER_BLOCK)  // 256 blocks

// smem layout (float2 units):
//   f_s  : [RANK][NPAIRS]  -> 10*1152 = 11520 float2  (92160 B)
//   fo_s : [OUTDIM][RANK/2] -> 512*5  =  2560 float2  (20480 B)
#define FS_ELEMS   (RANK * NPAIRS)
#define FO_ELEMS   (OUTDIM * (RANK / 2))
#define SMEM_BYTES ((FS_ELEMS + FO_ELEMS) * 8)

// ---------- f32x2 packed-math helpers (Blackwell sm_100+) ----------
__device__ __forceinline__ unsigned long long pk2(float lo, float hi) {
    unsigned long long r;
    asm("mov.b64 %0, {%1, %2};" : "=l"(r) : "f"(lo), "f"(hi));
    return r;
}
__device__ __forceinline__ void upk2(unsigned long long v, float& lo, float& hi) {
    asm("mov.b64 {%0, %1}, %2;" : "=f"(lo), "=f"(hi) : "l"(v));
}
__device__ __forceinline__ unsigned long long fma2(unsigned long long a,
                                                   unsigned long long b,
                                                   unsigned long long c) {
    unsigned long long d;
    asm("fma.rn.f32x2 %0, %1, %2, %3;" : "=l"(d) : "l"(a), "l"(b), "l"(c));
    return d;
}

// Rank-projection for one segment, 2 rows per thread, k-pair packed.
// fbase points at f_s + pair offset of this segment; row stride is NPAIRS.
// Accumulates z (lo=even-k partial, hi=odd-k partial) and multiplies the
// horizontal sum into y0/y1.
__device__ __forceinline__ void segment_accum(
    const float* __restrict__ x0, const float* __restrict__ x1,
    const unsigned long long* __restrict__ fbase,
    int kpairs, float* y0, float* y1, bool first)
{
    unsigned long long acc0[RANK], acc1[RANK];
#pragma unroll
    for (int r = 0; r < RANK; r++) { acc0[r] = 0ull; acc1[r] = 0ull; }

    // 2 k-pairs (4 floats) per iteration
    for (int i = 0; i < kpairs; i += 2) {
        float4 a0 = *reinterpret_cast<const float4*>(x0 + 2 * i);
        float4 a1 = *reinterpret_cast<const float4*>(x1 + 2 * i);
        unsigned long long a0p0 = pk2(a0.x, a0.y);
        unsigned long long a0p1 = pk2(a0.z, a0.w);
        unsigned long long a1p0 = pk2(a1.x, a1.y);
        unsigned long long a1p1 = pk2(a1.z, a1.w);
#pragma unroll
        for (int r = 0; r < RANK; r++) {
            unsigned long long fA = fbase[r * NPAIRS + i];
            unsigned long long fB = fbase[r * NPAIRS + i + 1];
            acc0[r] = fma2(a0p0, fA, acc0[r]);
            acc0[r] = fma2(a0p1, fB, acc0[r]);
            acc1[r] = fma2(a1p0, fA, acc1[r]);
            acc1[r] = fma2(a1p1, fB, acc1[r]);
        }
    }

#pragma unroll
    for (int r = 0; r < RANK; r++) {
        float lo, hi;
        upk2(acc0[r], lo, hi);
        float z0 = lo + hi;
        upk2(acc1[r], lo, hi);
        float z1 = lo + hi;
        if (first) { y0[r] = z0;  y1[r] = z1; }
        else       { y0[r] *= z0; y1[r] *= z1; }
    }
}

extern "C" __global__ void __launch_bounds__(THREADS)
arf_kernel(const float* __restrict__ x1, const float* __restrict__ x2,
           const float* __restrict__ x3,
           const float* __restrict__ f1, const float* __restrict__ f2,
           const float* __restrict__ f3, const float* __restrict__ fout,
           float* __restrict__ out)
{
    extern __shared__ float2 smem[];
    float2* f_s  = smem;              // [RANK][NPAIRS], pair-packed along k
    float2* fo_s = smem + FS_ELEMS;   // [OUTDIM][RANK/2], pair-packed along r

    const int tid = threadIdx.x;

    // ---- cooperative factor repack into smem ----
    // f_s[r*NPAIRS + kp] = (f_seg[2k][r], f_seg[2k+1][r])
    for (int idx = tid; idx < FS_ELEMS; idx += THREADS) {
        int r  = idx / NPAIRS;
        int kp = idx % NPAIRS;
        const float* f; int kloc;
        if (kp < K1 / 2)                 { f = f1; kloc = 2 * kp; }
        else if (kp < (K1 + K2) / 2)     { f = f2; kloc = 2 * (kp - K1 / 2); }
        else                             { f = f3; kloc = 2 * (kp - (K1 + K2) / 2); }
        f_s[idx] = make_float2(f[kloc * RANK + r], f[(kloc + 1) * RANK + r]);
    }
    // fo_s[c*5 + j] = (fout[c][2j], fout[c][2j+1])
    for (int idx = tid; idx < FO_ELEMS; idx += THREADS) {
        int c = idx / (RANK / 2);
        int j = idx % (RANK / 2);
        fo_s[idx] = make_float2(fout[c * RANK + 2 * j], fout[c * RANK + 2 * j + 1]);
    }
    __syncthreads();

    const unsigned long long* f_s64  = reinterpret_cast<const unsigned long long*>(f_s);
    const unsigned long long* fo_s64 = reinterpret_cast<const unsigned long long*>(fo_s);

    const int base = blockIdx.x * ROWS_PER_BLOCK;
    const int row0 = base + tid;
    const int row1 = base + tid + THREADS;

    float y0[RANK], y1[RANK];

    segment_accum(x1 + (size_t)row0 * K1, x1 + (size_t)row1 * K1,
                  f_s64 + 0,                K1 / 2, y0, y1, true);
    segment_accum(x2 + (size_t)row0 * K2, x2 + (size_t)row1 * K2,
                  f_s64 + K1 / 2,           K2 / 2, y0, y1, false);
    segment_accum(x3 + (size_t)row0 * K3, x3 + (size_t)row1 * K3,
                  f_s64 + (K1 + K2) / 2,    K3 / 2, y0, y1, false);

    // pack rank-pairs of y for the output GEMV
    unsigned long long yp0[RANK / 2], yp1[RANK / 2];
#pragma unroll
    for (int j = 0; j < RANK / 2; j++) {
        yp0[j] = pk2(y0[2 * j], y0[2 * j + 1]);
        yp1[j] = pk2(y1[2 * j], y1[2 * j + 1]);
    }

    float* o0 = out + (size_t)row0 * OUTDIM;
    float* o1 = out + (size_t)row1 * OUTDIM;

    for (int c = 0; c < OUTDIM; c += 4) {
        float4 r0, r1;
        float* r0p = &r0.x;
        float* r1p = &r1.x;
#pragma unroll
        for (int cc = 0; cc < 4; cc++) {
            unsigned long long s0 = 0ull, s1 = 0ull;
#pragma unroll
            for (int j = 0; j < RANK / 2; j++) {
                unsigned long long fv = fo_s64[(c + cc) * (RANK / 2) + j];
                s0 = fma2(yp0[j], fv, s0);
                s1 = fma2(yp1[j], fv, s1);
            }
            float lo, hi;
            upk2(s0, lo, hi); r0p[cc] = lo + hi;
            upk2(s1, lo, hi); r1p[cc] = lo + hi;
        }
        *reinterpret_cast<float4*>(o0 + c) = r0;
        *reinterpret_cast<float4*>(o1 + c) = r1;
    }
}

extern "C" void kernel_launch(void* const* d_in, const int* in_sizes, int n_in,
                              void* d_out, int out_size)
{
    const float* x1   = (const float*)d_in[0];
    const float* x2   = (const float*)d_in[1];
    const float* x3   = (const float*)d_in[2];
    const float* f1   = (const float*)d_in[3];
    const float* f2   = (const float*)d_in[4];
    const float* f3   = (const float*)d_in[5];
    const float* fout = (const float*)d_in[6];
    float* out = (float*)d_out;

    cudaFuncSetAttribute(arf_kernel,
                         cudaFuncAttributeMaxDynamicSharedMemorySize, SMEM_BYTES);

    arf_kernel<<<GRID, THREADS, SMEM_BYTES>>>(x1, x2, x3, f1, f2, f3, fout, out);
}

// round 2
// speedup vs baseline: 2.2373x; 2.2373x over previous
#include <cuda_runtime.h>
#include <cstdint>

// Problem constants
#define B_ROWS   65536
#define K1       1024
#define K2       512
#define K3       768
#define NPAIRS   1152                  // (K1+K2+K3)/2
#define RANK     10
#define OUTDIM   512

#define THREADS  256
#define GRID     304                   // 2 CTAs per SM on 152 SMs
#define NWARPS   (GRID * (THREADS / 32))
#define NPAIRS_ROWS (B_ROWS / 2)       // 32768 row-pairs

// smem: f_s [RANK][NPAIRS] float2 (k-pair packed, rank-major rows)
//       fo_s [OUTDIM][5]   float2 (rank-pair packed = raw fout)
#define FS_ELEMS   (RANK * NPAIRS)     // 11520 float2
#define FO_ELEMS   (OUTDIM * (RANK/2)) // 2560 float2
#define SMEM_BYTES ((FS_ELEMS + FO_ELEMS) * 8)   // 112640 B

typedef unsigned long long u64;

// ---------- f32x2 packed helpers ----------
__device__ __forceinline__ u64 pk2(float lo, float hi) {
    u64 r; asm("mov.b64 %0, {%1, %2};" : "=l"(r) : "f"(lo), "f"(hi)); return r;
}
__device__ __forceinline__ void upk2(u64 v, float& lo, float& hi) {
    asm("mov.b64 {%0, %1}, %2;" : "=f"(lo), "=f"(hi) : "l"(v));
}
__device__ __forceinline__ u64 fma2(u64 a, u64 b, u64 c) {
    u64 d; asm("fma.rn.f32x2 %0, %1, %2, %3;" : "=l"(d) : "l"(a), "l"(b), "l"(c));
    return d;
}
__device__ __forceinline__ float hadd2(u64 v) {
    float lo, hi; upk2(v, lo, hi); return lo + hi;
}

// One segment: warp processes rows (row0, row0+1) over KSEG columns.
// Lane handles k = c*128 + lane*4 .. +3 per chunk. Result: per-lane partial
// rank sums reduced across the warp into s0[], s1[] (all lanes hold result).
template<int KSEG, int PAIR_OFF>
__device__ __forceinline__ void segment(
    const float* __restrict__ x, int row0, int lane,
    const ulonglong2* __restrict__ f2, float* s0, float* s1)
{
    constexpr int NC = KSEG / 128;

    u64 acc0[RANK], acc1[RANK];
#pragma unroll
    for (int r = 0; r < RANK; r++) { acc0[r] = 0ull; acc1[r] = 0ull; }

    const float4* q0 = reinterpret_cast<const float4*>(x + (size_t)row0 * KSEG) + lane;
    const float4* q1 = q0 + (KSEG / 4);

    float4 A0 = q0[0];
    float4 A1 = q1[0];

#pragma unroll 2
    for (int c = 0; c < NC; c++) {
        float4 B0, B1;
        if (c + 1 < NC) {                 // prefetch next chunk (uniform branch)
            B0 = q0[(c + 1) * 32];
            B1 = q1[(c + 1) * 32];
        }
        u64 a0 = pk2(A0.x, A0.y);
        u64 a1 = pk2(A0.z, A0.w);
        u64 b0 = pk2(A1.x, A1.y);
        u64 b1 = pk2(A1.z, A1.w);

        const int base = PAIR_OFF + c * 64 + lane * 2;   // even
#pragma unroll
        for (int r = 0; r < RANK; r++) {
            ulonglong2 fv = f2[(r * NPAIRS + base) >> 1];  // LDS.128, contiguous/warp
            acc0[r] = fma2(a0, fv.x, acc0[r]);
            acc0[r] = fma2(a1, fv.y, acc0[r]);
            acc1[r] = fma2(b0, fv.x, acc1[r]);
            acc1[r] = fma2(b1, fv.y, acc1[r]);
        }
        A0 = B0; A1 = B1;
    }

    // fold even/odd then butterfly-reduce across the warp
#pragma unroll
    for (int r = 0; r < RANK; r++) { s0[r] = hadd2(acc0[r]); s1[r] = hadd2(acc1[r]); }
#pragma unroll
    for (int m = 16; m > 0; m >>= 1) {
#pragma unroll
        for (int r = 0; r < RANK; r++) {
            s0[r] += __shfl_xor_sync(0xffffffffu, s0[r], m);
            s1[r] += __shfl_xor_sync(0xffffffffu, s1[r], m);
        }
    }
}

extern "C" __global__ void __launch_bounds__(THREADS, 2)
arf_kernel(const float* __restrict__ x1, const float* __restrict__ x2,
           const float* __restrict__ x3,
           const float* __restrict__ f1, const float* __restrict__ f2,
           const float* __restrict__ f3, const float* __restrict__ fout,
           float* __restrict__ out)
{
    extern __shared__ float2 smem[];
    float2* f_s  = smem;               // [RANK][NPAIRS]
    float2* fo_s = smem + FS_ELEMS;    // [OUTDIM][5]

    const int tid  = threadIdx.x;
    const int lane = tid & 31;

    // ---- factor repack: f_s[r*NPAIRS + kp] = (f_seg[2k][r], f_seg[2k+1][r]) ----
    for (int idx = tid; idx < FS_ELEMS; idx += THREADS) {
        int r  = idx / NPAIRS;
        int kp = idx % NPAIRS;
        const float* f; int kloc;
        if (kp < K1 / 2)              { f = f1; kloc = 2 * kp; }
        else if (kp < (K1 + K2) / 2)  { f = f2; kloc = 2 * (kp - K1 / 2); }
        else                          { f = f3; kloc = 2 * (kp - (K1 + K2) / 2); }
        f_s[idx] = make_float2(f[kloc * RANK + r], f[(kloc + 1) * RANK + r]);
    }
    // fo_s = raw fout viewed as float2 (rank pairs)
    const float2* fo_g = reinterpret_cast<const float2*>(fout);
    for (int idx = tid; idx < FO_ELEMS; idx += THREADS) fo_s[idx] = fo_g[idx];
    __syncthreads();

    const ulonglong2* f2p  = reinterpret_cast<const ulonglong2*>(f_s);
    const u64*        fo64 = reinterpret_cast<const u64*>(fo_s);

    const int gw = (blockIdx.x * THREADS + tid) >> 5;

    for (int pr = gw; pr < NPAIRS_ROWS; pr += NWARPS) {
        const int row0 = pr * 2;

        float p0[RANK], p1[RANK], s0[RANK], s1[RANK];

        segment<K1, 0>            (x1, row0, lane, f2p, p0, p1);
        segment<K2, K1 / 2>       (x2, row0, lane, f2p, s0, s1);
#pragma unroll
        for (int r = 0; r < RANK; r++) { p0[r] *= s0[r]; p1[r] *= s1[r]; }
        segment<K3, (K1 + K2) / 2>(x3, row0, lane, f2p, s0, s1);
#pragma unroll
        for (int r = 0; r < RANK; r++) { p0[r] *= s0[r]; p1[r] *= s1[r]; }

        // rank-pair pack for the output GEMV
        u64 yp0[RANK / 2], yp1[RANK / 2];
#pragma unroll
        for (int j = 0; j < RANK / 2; j++) {
            yp0[j] = pk2(p0[2 * j], p0[2 * j + 1]);
            yp1[j] = pk2(p1[2 * j], p1[2 * j + 1]);
        }

        float* o0 = out + (size_t)row0 * OUTDIM;
        float* o1 = o0 + OUTDIM;

#pragma unroll 4
        for (int i = 0; i < OUTDIM / 32; i++) {
            const int c = i * 32 + lane;           // coalesced STG.32
            u64 a0 = 0ull, a1 = 0ull;
#pragma unroll
            for (int j = 0; j < RANK / 2; j++) {
                u64 fv = fo64[c * (RANK / 2) + j];  // conflict-free LDS.64
                a0 = fma2(yp0[j], fv, a0);
                a1 = fma2(yp1[j], fv, a1);
            }
            o0[c] = hadd2(a0);
            o1[c] = hadd2(a1);
        }
    }
}

extern "C" void kernel_launch(void* const* d_in, const int* in_sizes, int n_in,
                              void* d_out, int out_size)
{
    const float* x1   = (const float*)d_in[0];
    const float* x2   = (const float*)d_in[1];
    const float* x3   = (const float*)d_in[2];
    const float* f1   = (const float*)d_in[3];
    const float* f2   = (const float*)d_in[4];
    const float* f3   = (const float*)d_in[5];
    const float* fout = (const float*)d_in[6];
    float* out = (float*)d_out;

    cudaFuncSetAttribute(arf_kernel,
                         cudaFuncAttributeMaxDynamicSharedMemorySize, SMEM_BYTES);

    arf_kernel<<<GRID, THREADS, SMEM_BYTES>>>(x1, x2, x3, f1, f2, f3, fout, out);
}